// round 13
// baseline (speedup 1.0000x reference)
#include <cuda_runtime.h>
#include <cuda_fp16.h>
#include <math.h>

#define BB 8
#define SS 2048
#define EE 256
#define LL 4
#define FF 1024
#define NQ 8
#define NC 10
#define ROWS (BB*SS)   // 16384

// ---------------- scratch (static device arrays; no allocation) ----------------
__device__ float d_x[ROWS*EE];            // activations  (16 MB)
__device__ __half d_qh[ROWS*EE];          // quantum q, fp16 (8 MB)
__device__ __half d_w2h[LL*FF*EE];        // fp16 copy of W2 (4 MB)

#define MMA_F16(d, a0, a1, a2, a3, b0, b1)                                    \
    asm volatile(                                                             \
        "mma.sync.aligned.m16n8k16.row.col.f32.f16.f16.f32 "                  \
        "{%0,%1,%2,%3}, {%4,%5,%6,%7}, {%8,%9}, {%0,%1,%2,%3};"               \
        : "+f"(d[0]), "+f"(d[1]), "+f"(d[2]), "+f"(d[3])                      \
        : "r"(a0), "r"(a1), "r"(a2), "r"(a3), "r"(b0), "r"(b1))

__device__ __forceinline__ void ldsm4(unsigned& r0, unsigned& r1, unsigned& r2,
                                      unsigned& r3, unsigned a) {
    asm volatile("ldmatrix.sync.aligned.m8n8.x4.shared.b16 {%0,%1,%2,%3}, [%4];"
                 : "=r"(r0), "=r"(r1), "=r"(r2), "=r"(r3) : "r"(a));
}
__device__ __forceinline__ void ldsm4t(unsigned& r0, unsigned& r1, unsigned& r2,
                                       unsigned& r3, unsigned a) {
    asm volatile("ldmatrix.sync.aligned.m8n8.x4.trans.shared.b16 {%0,%1,%2,%3}, [%4];"
                 : "=r"(r0), "=r"(r1), "=r"(r2), "=r"(r3) : "r"(a));
}
__device__ __forceinline__ void cpasync16(unsigned dst, const void* src) {
    asm volatile("cp.async.cg.shared.global [%0], [%1], 16;" :: "r"(dst), "l"(src));
}
#define CP_COMMIT() asm volatile("cp.async.commit_group;" ::: "memory")
#define CP_WAIT1()  asm volatile("cp.async.wait_group 1;" ::: "memory")

// q-map: c_j = cos(v_j + phi_j); q_0 = prod_{j>=1} c_j; q_i = prod_{j<=i} c_j
__device__ __forceinline__ void qmap8(const float* v, const float* phi, float* out) {
    float c[8];
    #pragma unroll
    for (int i = 0; i < 8; i++) c[i] = cosf(v[i] + phi[i]);
    float t = c[1];
    #pragma unroll
    for (int j = 2; j < 8; j++) t *= c[j];
    out[0] = t;
    float pref = c[0];
    #pragma unroll
    for (int i = 1; i < 8; i++) { pref *= c[i]; out[i] = pref; }
}
__device__ __forceinline__ void store_q8(__half* qp, const float* out) {
    __half2* q2 = (__half2*)qp;
    q2[0] = __floats2half2_rn(out[0], out[1]);
    q2[1] = __floats2half2_rn(out[2], out[3]);
    q2[2] = __floats2half2_rn(out[4], out[5]);
    q2[3] = __floats2half2_rn(out[6], out[7]);
}

// ---------------- 0. W2 -> fp16 copy ----------------
__global__ void w2cvt_kernel(const float* __restrict__ W2) {
    int i = blockIdx.x * blockDim.x + threadIdx.x;
    float4 v = ((const float4*)W2)[i];
    __half2* dst = (__half2*)d_w2h;
    dst[2 * i]     = __floats2half2_rn(v.x, v.y);
    dst[2 * i + 1] = __floats2half2_rn(v.z, v.w);
}

// ---------------- 1. embedding + PE + layer-0 q (fused) ----------------
__global__ void embed_q_kernel(const int* __restrict__ tok, const float* __restrict__ emb,
                               const float* __restrict__ phi) {
    int g = blockIdx.x * blockDim.x + threadIdx.x;   // ROWS*32: (row, head)
    int row = g >> 5, h = g & 31;
    int s = row & (SS - 1);
    int base = row * EE + h * 8;
    const float4* er = (const float4*)(emb + (size_t)tok[row] * EE + h * 8);
    float4 e0 = er[0], e1 = er[1];
    float v[8] = {e0.x, e0.y, e0.z, e0.w, e1.x, e1.y, e1.z, e1.w};
    #pragma unroll
    for (int i = 0; i < 8; i++) {
        int e = h * 8 + i;
        float freq = expf((float)(e & ~1) * (-9.210340371976184f / 256.0f));
        float ang = (float)s * freq;
        v[i] += (e & 1) ? cosf(ang) : sinf(ang);
    }
    *(float4*)(d_x + base)     = make_float4(v[0], v[1], v[2], v[3]);
    *(float4*)(d_x + base + 4) = make_float4(v[4], v[5], v[6], v[7]);
    float out[8];
    qmap8(v, phi, out);
    store_q8(d_qh + base, out);
}

// ---------------- 2. fp16 flash attention + fused residual LayerNorm ----------------
// (identical to the R12 passing version)
#define NSTG 3
#define KP 264                        // Ks row stride (halves)
#define SST 68                        // Sb row stride (fp32)
#define KS_BYTES (64 * KP * 2)        // 33792 per stage
#define SB_OFF (NSTG * KS_BYTES)      // 101376
#define SB_BYTES (8 * 16 * SST * 4)   // 34816
#define RED_OFF (SB_OFF + SB_BYTES)   // 136192
#define GS_OFF (RED_OFF + 1024)
#define BS_OFF (GS_OFF + 1024)
#define ATT_SMEM (BS_OFF + 1024)      // 139264

__global__ __launch_bounds__(256, 1) void attn_kernel(const float* __restrict__ gam,
                                                      const float* __restrict__ bet) {
    extern __shared__ char smc[];
    float* Sb = (float*)(smc + SB_OFF);
    float2* red = (float2*)(smc + RED_OFF);
    float* gs = (float*)(smc + GS_OFF);
    float* bs = (float*)(smc + BS_OFF);
    const unsigned ks_s = (unsigned)__cvta_generic_to_shared(smc);

    const int tid = threadIdx.x;
    const int w = tid >> 5, lane = tid & 31;
    const int qt = lane >> 2, tq = lane & 3;
    const int eh = w & 1;
    const int b = blockIdx.y;
    const int row0 = blockIdx.x * 64 + (w >> 1) * 16;
    const __half* qbb = d_qh + (size_t)b * SS * EE;
    const float C = 0.51006977f;   // log2(e)/sqrt(8)

    gs[tid] = gam[tid];
    bs[tid] = bet[tid];

    unsigned qa[8][4];
    {
        const __half* p0 = qbb + (size_t)(row0 + qt) * EE + eh * 128 + 2 * tq;
        #pragma unroll
        for (int k = 0; k < 8; k++) {
            qa[k][0] = *(const unsigned*)(p0 + 16 * k);
            qa[k][1] = *(const unsigned*)(p0 + 8 * EE + 16 * k);
            qa[k][2] = *(const unsigned*)(p0 + 16 * k + 8);
            qa[k][3] = *(const unsigned*)(p0 + 8 * EE + 16 * k + 8);
        }
    }
    float o[16][4];
    #pragma unroll
    for (int n = 0; n < 16; n++) { o[n][0] = o[n][1] = o[n][2] = o[n][3] = 0.f; }
    float m0 = -1e30f, m1 = -1e30f, l0 = 0.f, l1 = 0.f;

    float* Sw = Sb + w * 16 * SST;
    float* Sp = Sb + (w ^ 1) * 16 * SST;

    const int l7 = lane & 7, l3 = lane >> 3;
    const unsigned qk_off = 2u * (unsigned)(l7 * KP + eh * 128 + 8 * l3);
    const unsigned pv_off = 2u * (unsigned)((l7 + 8 * (l3 & 1)) * KP + eh * 128 + 8 * (l3 >> 1));

    #pragma unroll
    for (int t = 0; t < 2; t++) {
        const uint4* src = (const uint4*)(qbb + (size_t)t * 64 * EE);
        const unsigned dst = ks_s + (unsigned)(t * KS_BYTES);
        #pragma unroll
        for (int p = 0; p < 8; p++) {
            int idx = p * 256 + tid;
            cpasync16(dst + 2u * (unsigned)((idx >> 5) * KP + (idx & 31) * 8), src + idx);
        }
        CP_COMMIT();
    }

    int cur = 0;
    for (int kt = 0; kt < SS / 64; kt++) {
        CP_WAIT1();
        __syncthreads();

        if (kt + 2 < SS / 64) {
            int nxt = cur + 2; if (nxt >= NSTG) nxt -= NSTG;
            const uint4* src = (const uint4*)(qbb + (size_t)(kt + 2) * 64 * EE);
            const unsigned dst = ks_s + (unsigned)(nxt * KS_BYTES);
            #pragma unroll
            for (int p = 0; p < 8; p++) {
                int idx = p * 256 + tid;
                cpasync16(dst + 2u * (unsigned)((idx >> 5) * KP + (idx & 31) * 8), src + idx);
            }
        }
        CP_COMMIT();

        const unsigned ks_cur = ks_s + (unsigned)(cur * KS_BYTES);

        float sc[8][4];
        #pragma unroll
        for (int n = 0; n < 8; n++) { sc[n][0] = sc[n][1] = sc[n][2] = sc[n][3] = 0.f; }
        #pragma unroll
        for (int n = 0; n < 8; n++) {
            unsigned base = ks_cur + qk_off + (unsigned)(n * 8 * KP * 2);
            #pragma unroll
            for (int kk = 0; kk < 4; kk++) {
                unsigned b0, b1, b2, b3;
                ldsm4(b0, b1, b2, b3, base + kk * 64);
                MMA_F16(sc[n], qa[2*kk][0], qa[2*kk][1], qa[2*kk][2], qa[2*kk][3], b0, b1);
                MMA_F16(sc[n], qa[2*kk+1][0], qa[2*kk+1][1], qa[2*kk+1][2], qa[2*kk+1][3], b2, b3);
            }
        }

        #pragma unroll
        for (int n = 0; n < 8; n++) {
            *(float2*)(Sw + qt * SST + n * 8 + 2 * tq)       = make_float2(sc[n][0], sc[n][1]);
            *(float2*)(Sw + (qt + 8) * SST + n * 8 + 2 * tq) = make_float2(sc[n][2], sc[n][3]);
        }
        __syncthreads();
        #pragma unroll
        for (int n = 0; n < 8; n++) {
            float2 p0 = *(const float2*)(Sp + qt * SST + n * 8 + 2 * tq);
            float2 p1 = *(const float2*)(Sp + (qt + 8) * SST + n * 8 + 2 * tq);
            sc[n][0] += p0.x; sc[n][1] += p0.y;
            sc[n][2] += p1.x; sc[n][3] += p1.y;
        }

        float mx0 = sc[0][0], mx1 = sc[0][2];
        #pragma unroll
        for (int n = 0; n < 8; n++) {
            mx0 = fmaxf(mx0, fmaxf(sc[n][0], sc[n][1]));
            mx1 = fmaxf(mx1, fmaxf(sc[n][2], sc[n][3]));
        }
        mx0 = fmaxf(mx0, __shfl_xor_sync(0xffffffffu, mx0, 1));
        mx0 = fmaxf(mx0, __shfl_xor_sync(0xffffffffu, mx0, 2));
        mx1 = fmaxf(mx1, __shfl_xor_sync(0xffffffffu, mx1, 1));
        mx1 = fmaxf(mx1, __shfl_xor_sync(0xffffffffu, mx1, 2));
        float nm0 = fmaxf(m0, mx0), nm1 = fmaxf(m1, mx1);
        if (__ballot_sync(0xffffffffu, (nm0 > m0) | (nm1 > m1))) {
            float c0 = exp2f((m0 - nm0) * C), c1 = exp2f((m1 - nm1) * C);
            l0 *= c0; l1 *= c1;
            #pragma unroll
            for (int n = 0; n < 16; n++) {
                o[n][0] *= c0; o[n][1] *= c0; o[n][2] *= c1; o[n][3] *= c1;
            }
        }
        m0 = nm0; m1 = nm1;

        unsigned pa[4][4];
        float s0 = 0.f, s1 = 0.f;
        #pragma unroll
        for (int kk = 0; kk < 4; kk++) {
            int n0 = 2 * kk, n1 = 2 * kk + 1;
            __half2 h;
            h = __floats2half2_rn(exp2f((sc[n0][0] - m0) * C), exp2f((sc[n0][1] - m0) * C));
            pa[kk][0] = *(unsigned*)&h; s0 += __low2float(h) + __high2float(h);
            h = __floats2half2_rn(exp2f((sc[n0][2] - m1) * C), exp2f((sc[n0][3] - m1) * C));
            pa[kk][1] = *(unsigned*)&h; s1 += __low2float(h) + __high2float(h);
            h = __floats2half2_rn(exp2f((sc[n1][0] - m0) * C), exp2f((sc[n1][1] - m0) * C));
            pa[kk][2] = *(unsigned*)&h; s0 += __low2float(h) + __high2float(h);
            h = __floats2half2_rn(exp2f((sc[n1][2] - m1) * C), exp2f((sc[n1][3] - m1) * C));
            pa[kk][3] = *(unsigned*)&h; s1 += __low2float(h) + __high2float(h);
        }
        s0 += __shfl_xor_sync(0xffffffffu, s0, 1);
        s0 += __shfl_xor_sync(0xffffffffu, s0, 2);
        s1 += __shfl_xor_sync(0xffffffffu, s1, 1);
        s1 += __shfl_xor_sync(0xffffffffu, s1, 2);
        l0 += s0; l1 += s1;

        #pragma unroll
        for (int np = 0; np < 8; np++) {
            unsigned base = ks_cur + pv_off + (unsigned)(np * 32);
            #pragma unroll
            for (int kk = 0; kk < 4; kk++) {
                unsigned b0, b1, b2, b3;
                ldsm4t(b0, b1, b2, b3, base + (unsigned)(kk * 16 * KP * 2));
                MMA_F16(o[2*np],   pa[kk][0], pa[kk][1], pa[kk][2], pa[kk][3], b0, b1);
                MMA_F16(o[2*np+1], pa[kk][0], pa[kk][1], pa[kk][2], pa[kk][3], b2, b3);
            }
        }
        cur = (cur + 1 == NSTG) ? 0 : cur + 1;
    }

    float i0 = 1.f / l0, i1 = 1.f / l1;
    float* xr0 = d_x + ((size_t)b * SS + row0 + qt) * EE;
    float* xr1 = d_x + ((size_t)b * SS + row0 + qt + 8) * EE;
    float sum0 = 0.f, sq0 = 0.f, sum1 = 0.f, sq1 = 0.f;
    #pragma unroll
    for (int n = 0; n < 16; n++) {
        int col = eh * 128 + n * 8 + 2 * tq;
        float2 x0 = *(const float2*)(xr0 + col);
        float2 x1 = *(const float2*)(xr1 + col);
        o[n][0] = o[n][0] * i0 + x0.x;  o[n][1] = o[n][1] * i0 + x0.y;
        o[n][2] = o[n][2] * i1 + x1.x;  o[n][3] = o[n][3] * i1 + x1.y;
        sum0 += o[n][0] + o[n][1]; sq0 += o[n][0] * o[n][0] + o[n][1] * o[n][1];
        sum1 += o[n][2] + o[n][3]; sq1 += o[n][2] * o[n][2] + o[n][3] * o[n][3];
    }
    #pragma unroll
    for (int mask = 1; mask <= 2; mask <<= 1) {
        sum0 += __shfl_xor_sync(0xffffffffu, sum0, mask);
        sq0  += __shfl_xor_sync(0xffffffffu, sq0, mask);
        sum1 += __shfl_xor_sync(0xffffffffu, sum1, mask);
        sq1  += __shfl_xor_sync(0xffffffffu, sq1, mask);
    }
    int pair = w >> 1;
    if (tq == 0) {
        red[(pair * 16 + qt) * 2 + eh]     = make_float2(sum0, sq0);
        red[(pair * 16 + qt + 8) * 2 + eh] = make_float2(sum1, sq1);
    }
    __syncthreads();
    float2 ra = red[(pair * 16 + qt) * 2 + 0], rb = red[(pair * 16 + qt) * 2 + 1];
    float mean0 = (ra.x + rb.x) * (1.f / EE);
    float var0 = (ra.y + rb.y) * (1.f / EE) - mean0 * mean0;
    float rv0 = rsqrtf(var0 + 1e-5f);
    float2 rc = red[(pair * 16 + qt + 8) * 2 + 0], rd = red[(pair * 16 + qt + 8) * 2 + 1];
    float mean1 = (rc.x + rd.x) * (1.f / EE);
    float var1 = (rc.y + rd.y) * (1.f / EE) - mean1 * mean1;
    float rv1 = rsqrtf(var1 + 1e-5f);
    #pragma unroll
    for (int n = 0; n < 16; n++) {
        int col = eh * 128 + n * 8 + 2 * tq;
        float2 gv = *(const float2*)(gs + col);
        float2 bv = *(const float2*)(bs + col);
        *(float2*)(xr0 + col) = make_float2((o[n][0] - mean0) * rv0 * gv.x + bv.x,
                                            (o[n][1] - mean0) * rv0 * gv.y + bv.y);
        *(float2*)(xr1 + col) = make_float2((o[n][2] - mean1) * rv1 * gv.x + bv.x,
                                            (o[n][3] - mean1) * rv1 * gv.y + bv.y);
    }
}

// ---------------- 3. fused FFN + residual LN2 + next-layer qmap ----------------
// CTA: 64 rows x 256 cols; warp = 32 rows x 64 cols; K-tile = 64 (dynamic smem).
// Epilogue: v = f + b2 + x; x = LN(v)*g2+be2 -> d_x; qmap(x) -> d_qh (2 batches
// of 32 rows staged through the dead ws region).
#define HSP 72    // hs row stride (halves)
#define WSP 264   // ws row stride (halves)
#define XSP 264   // xs row stride (floats), xs reuses ws region
#define FFN_W1_OFF  2304                       // qm float[64][9]
#define FFN_B1_OFF  (FFN_W1_OFF + 2112)        // w1s float[8][66]
#define FFN_B2_OFF  (FFN_B1_OFF + 4096)        // b1s float[1024]
#define FFN_G2_OFF  (FFN_B2_OFF + 1024)        // b2s float[256]
#define FFN_BE2_OFF (FFN_G2_OFF + 1024)        // g2s float[256]
#define FFN_RED_OFF (FFN_BE2_OFF + 1024)       // be2s float[256]
#define FFN_HS_OFF  (FFN_RED_OFF + 2048)       // red float2[64][4]
#define FFN_WS_OFF  (FFN_HS_OFF + 64*HSP*2)    // hs half[64][72]
#define FFN_SMEM    (FFN_WS_OFF + 64*WSP*2)    // ws half[64][264] => 56640 B

__global__ __launch_bounds__(256, 2) void ffn_kernel(const float* __restrict__ theta,
                                                     const float* __restrict__ W1,
                                                     const float* __restrict__ b1,
                                                     int layer,
                                                     const float* __restrict__ b2,
                                                     const float* __restrict__ gam2,
                                                     const float* __restrict__ bet2,
                                                     const float* __restrict__ phiN) {
    extern __shared__ char fsm[];
    float* qm   = (float*)fsm;                        // [64][9]
    float* w1s  = (float*)(fsm + FFN_W1_OFF);         // [8][66]
    float* b1s  = (float*)(fsm + FFN_B1_OFF);         // [1024]
    float* b2s  = (float*)(fsm + FFN_B2_OFF);         // [256]
    float* g2s  = (float*)(fsm + FFN_G2_OFF);         // [256]
    float* be2s = (float*)(fsm + FFN_BE2_OFF);        // [256]
    float2* redp = (float2*)(fsm + FFN_RED_OFF);      // [64][4]
    __half* hs  = (__half*)(fsm + FFN_HS_OFF);        // [64][HSP]
    __half* ws  = (__half*)(fsm + FFN_WS_OFF);        // [64][WSP]
    float*  xs  = (float*)(fsm + FFN_WS_OFF);         // [32][XSP] (reuse)

    const __half* __restrict__ W2h = d_w2h + (size_t)layer * FF * EE;
    const int t = threadIdx.x, w = t >> 5, lane = t & 31;
    const int qt = lane >> 2, tq = lane & 3;
    const int l7 = lane & 7, l3 = lane >> 3;
    const int wm = w >> 2, wn = w & 3;
    const int rowBase = blockIdx.x * 64;
    const unsigned hs_s = (unsigned)__cvta_generic_to_shared(hs);
    const unsigned ws_s = (unsigned)__cvta_generic_to_shared(ws);

    b2s[t] = b2[t];
    g2s[t] = gam2[t];
    be2s[t] = bet2[t];
    #pragma unroll
    for (int p = 0; p < 4; p++) b1s[t + p * 256] = b1[t + p * 256];
    #pragma unroll
    for (int i = 0; i < 2; i++) {
        int idx = t * 2 + i;
        int r = idx >> 3, j = idx & 7;
        qm[r * 9 + j] = cosf(d_x[(size_t)(rowBase + r) * EE + j]) * cosf(theta[j]);
    }

    float c[2][8][4];
    #pragma unroll
    for (int mt = 0; mt < 2; mt++)
        #pragma unroll
        for (int nt = 0; nt < 8; nt++)
            c[mt][nt][0] = c[mt][nt][1] = c[mt][nt][2] = c[mt][nt][3] = 0.f;

    for (int kt = 0; kt < FF / 64; kt++) {
        int k0g = kt * 64;
        __syncthreads();
        {   // W1 tile 8x64
            #pragma unroll
            for (int p = 0; p < 2; p++) {
                int idx = p * 256 + t;
                w1s[(idx >> 6) * 66 + (idx & 63)] = W1[(idx >> 6) * FF + k0g + (idx & 63)];
            }
        }
        {   // W2 fp16 tile 64x256
            const uint4* w4 = (const uint4*)(W2h + (size_t)k0g * EE);
            #pragma unroll
            for (int p = 0; p < 8; p++) {
                int idx = p * 256 + t;
                *(uint4*)(&ws[(idx >> 5) * WSP + (idx & 31) * 8]) = w4[idx];
            }
        }
        __syncthreads();
        {   // hidden tile 64x64 via fused ffn1 (fp32 math -> fp16 store)
            int r = t & 63, cg = (t >> 6) * 16;
            #pragma unroll
            for (int i = 0; i < 16; i++) {
                int cc = cg + i;
                float h = b1s[k0g + cc];
                #pragma unroll
                for (int j = 0; j < 8; j++) h += qm[r * 9 + j] * w1s[j * 66 + cc];
                hs[r * HSP + cc] = __float2half(fmaxf(h, 0.f));
            }
        }
        __syncthreads();
        #pragma unroll
        for (int ks = 0; ks < 4; ks++) {
            unsigned a[2][4];
            #pragma unroll
            for (int mt = 0; mt < 2; mt++) {
                int mrow = wm * 32 + mt * 16;
                unsigned addr = hs_s + 2u * (unsigned)((mrow + l7 + 8 * (l3 & 1)) * HSP +
                                                       ks * 16 + 8 * (l3 >> 1));
                ldsm4(a[mt][0], a[mt][1], a[mt][2], a[mt][3], addr);
            }
            #pragma unroll
            for (int ng = 0; ng < 4; ng++) {
                int n0 = wn * 64 + ng * 16;
                unsigned baddr = ws_s + 2u * (unsigned)((ks * 16 + l7 + 8 * (l3 & 1)) * WSP +
                                                        n0 + 8 * (l3 >> 1));
                unsigned b0, b1r, b2r, b3;
                ldsm4t(b0, b1r, b2r, b3, baddr);
                MMA_F16(c[0][2*ng],   a[0][0], a[0][1], a[0][2], a[0][3], b0, b1r);
                MMA_F16(c[0][2*ng+1], a[0][0], a[0][1], a[0][2], a[0][3], b2r, b3);
                MMA_F16(c[1][2*ng],   a[1][0], a[1][1], a[1][2], a[1][3], b0, b1r);
                MMA_F16(c[1][2*ng+1], a[1][0], a[1][1], a[1][2], a[1][3], b2r, b3);
            }
        }
    }

    // ---- fused epilogue: v = f + b2 + x ; x = LN(v) ; write d_x ; qmap ----
    float sum[2][2] = {{0.f, 0.f}, {0.f, 0.f}};
    float sq[2][2]  = {{0.f, 0.f}, {0.f, 0.f}};
    #pragma unroll
    for (int mt = 0; mt < 2; mt++) {
        int gr = rowBase + wm * 32 + mt * 16;
        #pragma unroll
        for (int nt = 0; nt < 8; nt++) {
            int col = wn * 64 + nt * 8 + 2 * tq;
            float2 x0 = *(const float2*)(d_x + (size_t)(gr + qt) * EE + col);
            float2 x1 = *(const float2*)(d_x + (size_t)(gr + qt + 8) * EE + col);
            float bb0 = b2s[col], bb1 = b2s[col + 1];
            c[mt][nt][0] += bb0 + x0.x;  c[mt][nt][1] += bb1 + x0.y;
            c[mt][nt][2] += bb0 + x1.x;  c[mt][nt][3] += bb1 + x1.y;
            sum[mt][0] += c[mt][nt][0] + c[mt][nt][1];
            sq[mt][0]  += c[mt][nt][0] * c[mt][nt][0] + c[mt][nt][1] * c[mt][nt][1];
            sum[mt][1] += c[mt][nt][2] + c[mt][nt][3];
            sq[mt][1]  += c[mt][nt][2] * c[mt][nt][2] + c[mt][nt][3] * c[mt][nt][3];
        }
    }
    #pragma unroll
    for (int mask = 1; mask <= 2; mask <<= 1) {
        #pragma unroll
        for (int mt = 0; mt < 2; mt++) {
            #pragma unroll
            for (int rh = 0; rh < 2; rh++) {
                sum[mt][rh] += __shfl_xor_sync(0xffffffffu, sum[mt][rh], mask);
                sq[mt][rh]  += __shfl_xor_sync(0xffffffffu, sq[mt][rh], mask);
            }
        }
    }
    if (tq == 0) {
        #pragma unroll
        for (int mt = 0; mt < 2; mt++)
            #pragma unroll
            for (int rh = 0; rh < 2; rh++)
                redp[(wm * 32 + mt * 16 + qt + rh * 8) * 4 + wn] =
                    make_float2(sum[mt][rh], sq[mt][rh]);
    }
    __syncthreads();
    float mean[2][2], rv[2][2];
    #pragma unroll
    for (int mt = 0; mt < 2; mt++) {
        #pragma unroll
        for (int rh = 0; rh < 2; rh++) {
            int row = wm * 32 + mt * 16 + qt + rh * 8;
            float2 r0 = redp[row * 4 + 0], r1 = redp[row * 4 + 1];
            float2 r2 = redp[row * 4 + 2], r3 = redp[row * 4 + 3];
            float s = r0.x + r1.x + r2.x + r3.x;
            float q = r0.y + r1.y + r2.y + r3.y;
            float mn = s * (1.f / EE);
            mean[mt][rh] = mn;
            rv[mt][rh] = rsqrtf(q * (1.f / EE) - mn * mn + 1e-5f);
        }
    }
    // apply LN in-register + write d_x
    #pragma unroll
    for (int mt = 0; mt < 2; mt++) {
        int gr = rowBase + wm * 32 + mt * 16;
        #pragma unroll
        for (int nt = 0; nt < 8; nt++) {
            int col = wn * 64 + nt * 8 + 2 * tq;
            float g0 = g2s[col], g1v = g2s[col + 1];
            float e0 = be2s[col], e1 = be2s[col + 1];
            c[mt][nt][0] = (c[mt][nt][0] - mean[mt][0]) * rv[mt][0] * g0 + e0;
            c[mt][nt][1] = (c[mt][nt][1] - mean[mt][0]) * rv[mt][0] * g1v + e1;
            c[mt][nt][2] = (c[mt][nt][2] - mean[mt][1]) * rv[mt][1] * g0 + e0;
            c[mt][nt][3] = (c[mt][nt][3] - mean[mt][1]) * rv[mt][1] * g1v + e1;
            *(float2*)(d_x + (size_t)(gr + qt) * EE + col) =
                make_float2(c[mt][nt][0], c[mt][nt][1]);
            *(float2*)(d_x + (size_t)(gr + qt + 8) * EE + col) =
                make_float2(c[mt][nt][2], c[mt][nt][3]);
        }
    }
    // next-layer q: stage 32-row batches through xs, qmap cooperatively
    if (phiN) {
        #pragma unroll
        for (int bi = 0; bi < 2; bi++) {
            __syncthreads();          // xs (ws region) free / prev batch consumed
            if (wm == bi) {
                #pragma unroll
                for (int mt = 0; mt < 2; mt++) {
                    int lr = mt * 16;
                    #pragma unroll
                    for (int nt = 0; nt < 8; nt++) {
                        int col = wn * 64 + nt * 8 + 2 * tq;
                        *(float2*)(xs + (lr + qt) * XSP + col) =
                            make_float2(c[mt][nt][0], c[mt][nt][1]);
                        *(float2*)(xs + (lr + qt + 8) * XSP + col) =
                            make_float2(c[mt][nt][2], c[mt][nt][3]);
                    }
                }
            }
            __syncthreads();
            #pragma unroll
            for (int k2 = 0; k2 < 4; k2++) {
                int task = t + k2 * 256;          // 1024 = 32 rows x 32 heads
                int row = task >> 5, head = task & 31;
                const float* xp = xs + row * XSP + head * 8;
                float v8[8];
                #pragma unroll
                for (int i = 0; i < 8; i++) v8[i] = xp[i];
                float out[8];
                qmap8(v8, phiN, out);
                store_q8(d_qh + (size_t)(rowBase + bi * 32 + row) * EE + head * 8, out);
            }
        }
    }
}

// ---------------- 4. mean over S + classifier head ----------------
__global__ void head_kernel(const float* __restrict__ Wc, const float* __restrict__ bc,
                            float* __restrict__ out) {
    __shared__ float sm[1024];
    __shared__ float mean[EE];
    int b = blockIdx.x;
    int e = threadIdx.x & 255;
    int chunk = threadIdx.x >> 8;
    float s = 0.f;
    for (int i = 0; i < SS / 4; i++) {
        int srow = chunk * (SS / 4) + i;
        s += d_x[((size_t)b * SS + srow) * EE + e];
    }
    sm[threadIdx.x] = s;
    __syncthreads();
    if (threadIdx.x < 256) {
        float tot = sm[e] + sm[e + 256] + sm[e + 512] + sm[e + 768];
        mean[e] = tot * (1.f / SS);
    }
    __syncthreads();
    if (threadIdx.x < NC) {
        float acc = bc[threadIdx.x];
        for (int ee = 0; ee < EE; ee++)
            acc += mean[ee] * Wc[ee * NC + threadIdx.x];
        out[b * NC + threadIdx.x] = acc;
    }
}

// ---------------- launch ----------------
extern "C" void kernel_launch(void* const* d_in, const int* in_sizes, int n_in,
                              void* d_out, int out_size) {
    const int*   tok   = (const int*)d_in[0];
    const float* emb   = (const float*)d_in[1];
    const float* phi   = (const float*)d_in[2];
    const float* theta = (const float*)d_in[3];
    const float* W1    = (const float*)d_in[4];
    const float* b1    = (const float*)d_in[5];
    const float* W2    = (const float*)d_in[6];
    const float* b2    = (const float*)d_in[7];
    const float* g1    = (const float*)d_in[8];
    const float* be1   = (const float*)d_in[9];
    const float* g2    = (const float*)d_in[10];
    const float* be2   = (const float*)d_in[11];
    const float* Wc    = (const float*)d_in[12];
    const float* bc    = (const float*)d_in[13];
    float* out = (float*)d_out;

    cudaFuncSetAttribute(attn_kernel, cudaFuncAttributeMaxDynamicSharedMemorySize, ATT_SMEM);
    cudaFuncSetAttribute(ffn_kernel, cudaFuncAttributeMaxDynamicSharedMemorySize, FFN_SMEM);

    w2cvt_kernel<<<LL * FF * EE / 4 / 256, 256>>>(W2);
    embed_q_kernel<<<ROWS * 32 / 256, 256>>>(tok, emb, phi);
    for (int l = 0; l < LL; l++) {
        attn_kernel<<<dim3(SS / 64, BB), 256, ATT_SMEM>>>(g1 + l * EE, be1 + l * EE);
        ffn_kernel<<<ROWS / 64, 256, FFN_SMEM>>>(theta + l * NQ, W1 + (size_t)l * NQ * FF,
                                                 b1 + l * FF, l, b2 + l * EE,
                                                 g2 + l * EE, be2 + l * EE,
                                                 (l < LL - 1) ? (phi + (l + 1) * NQ) : nullptr);
    }
    head_kernel<<<BB, 1024>>>(Wc, bc, out);
}

// round 14
// speedup vs baseline: 1.0143x; 1.0143x over previous
#include <cuda_runtime.h>
#include <cuda_fp16.h>
#include <math.h>

#define BB 8
#define SS 2048
#define EE 256
#define LL 4
#define FF 1024
#define NQ 8
#define NC 10
#define ROWS (BB*SS)   // 16384

// ---------------- scratch (static device arrays; no allocation) ----------------
__device__ float d_x[ROWS*EE];            // activations  (16 MB)
__device__ __half d_qh[ROWS*EE];          // quantum q, fp16 (8 MB)
__device__ __half d_w2h[LL*FF*EE];        // fp16 copy of W2 (4 MB)
__device__ float d_part[BB*32*EE];        // head partial sums (256 KB)

#define MMA_F16(d, a0, a1, a2, a3, b0, b1)                                    \
    asm volatile(                                                             \
        "mma.sync.aligned.m16n8k16.row.col.f32.f16.f16.f32 "                  \
        "{%0,%1,%2,%3}, {%4,%5,%6,%7}, {%8,%9}, {%0,%1,%2,%3};"               \
        : "+f"(d[0]), "+f"(d[1]), "+f"(d[2]), "+f"(d[3])                      \
        : "r"(a0), "r"(a1), "r"(a2), "r"(a3), "r"(b0), "r"(b1))

__device__ __forceinline__ void ldsm4(unsigned& r0, unsigned& r1, unsigned& r2,
                                      unsigned& r3, unsigned a) {
    asm volatile("ldmatrix.sync.aligned.m8n8.x4.shared.b16 {%0,%1,%2,%3}, [%4];"
                 : "=r"(r0), "=r"(r1), "=r"(r2), "=r"(r3) : "r"(a));
}
__device__ __forceinline__ void ldsm4t(unsigned& r0, unsigned& r1, unsigned& r2,
                                       unsigned& r3, unsigned a) {
    asm volatile("ldmatrix.sync.aligned.m8n8.x4.trans.shared.b16 {%0,%1,%2,%3}, [%4];"
                 : "=r"(r0), "=r"(r1), "=r"(r2), "=r"(r3) : "r"(a));
}
__device__ __forceinline__ void cpasync16(unsigned dst, const void* src) {
    asm volatile("cp.async.cg.shared.global [%0], [%1], 16;" :: "r"(dst), "l"(src));
}
#define CP_COMMIT() asm volatile("cp.async.commit_group;" ::: "memory")
#define CP_WAIT1()  asm volatile("cp.async.wait_group 1;" ::: "memory")

// q-map: c_j = cos(v_j + phi_j); q_0 = prod_{j>=1} c_j; q_i = prod_{j<=i} c_j
__device__ __forceinline__ void qmap8(const float* v, const float* phi, float* out) {
    float c[8];
    #pragma unroll
    for (int i = 0; i < 8; i++) c[i] = cosf(v[i] + phi[i]);
    float t = c[1];
    #pragma unroll
    for (int j = 2; j < 8; j++) t *= c[j];
    out[0] = t;
    float pref = c[0];
    #pragma unroll
    for (int i = 1; i < 8; i++) { pref *= c[i]; out[i] = pref; }
}
__device__ __forceinline__ void store_q8(__half* qp, const float* out) {
    __half2* q2 = (__half2*)qp;
    q2[0] = __floats2half2_rn(out[0], out[1]);
    q2[1] = __floats2half2_rn(out[2], out[3]);
    q2[2] = __floats2half2_rn(out[4], out[5]);
    q2[3] = __floats2half2_rn(out[6], out[7]);
}

// ---------------- 0. W2 -> fp16 copy ----------------
__global__ void w2cvt_kernel(const float* __restrict__ W2) {
    int i = blockIdx.x * blockDim.x + threadIdx.x;
    float4 v = ((const float4*)W2)[i];
    __half2* dst = (__half2*)d_w2h;
    dst[2 * i]     = __floats2half2_rn(v.x, v.y);
    dst[2 * i + 1] = __floats2half2_rn(v.z, v.w);
}

// ---------------- 1. embedding + PE + layer-0 q (fused) ----------------
__global__ void embed_q_kernel(const int* __restrict__ tok, const float* __restrict__ emb,
                               const float* __restrict__ phi) {
    int g = blockIdx.x * blockDim.x + threadIdx.x;   // ROWS*32: (row, head)
    int row = g >> 5, h = g & 31;
    int s = row & (SS - 1);
    int base = row * EE + h * 8;
    const float4* er = (const float4*)(emb + (size_t)tok[row] * EE + h * 8);
    float4 e0 = er[0], e1 = er[1];
    float v[8] = {e0.x, e0.y, e0.z, e0.w, e1.x, e1.y, e1.z, e1.w};
    #pragma unroll
    for (int i = 0; i < 8; i++) {
        int e = h * 8 + i;
        float freq = expf((float)(e & ~1) * (-9.210340371976184f / 256.0f));
        float ang = (float)s * freq;
        v[i] += (e & 1) ? cosf(ang) : sinf(ang);
    }
    *(float4*)(d_x + base)     = make_float4(v[0], v[1], v[2], v[3]);
    *(float4*)(d_x + base + 4) = make_float4(v[4], v[5], v[6], v[7]);
    float out[8];
    qmap8(v, phi, out);
    store_q8(d_qh + base, out);
}

// ---------------- 2. fp16 flash attention + fused residual LayerNorm ----------------
// (identical to the R12/R13 passing version)
#define NSTG 3
#define KP 264                        // Ks row stride (halves)
#define SST 68                        // Sb row stride (fp32)
#define KS_BYTES (64 * KP * 2)        // 33792 per stage
#define SB_OFF (NSTG * KS_BYTES)      // 101376
#define SB_BYTES (8 * 16 * SST * 4)   // 34816
#define RED_OFF (SB_OFF + SB_BYTES)   // 136192
#define GS_OFF (RED_OFF + 1024)
#define BS_OFF (GS_OFF + 1024)
#define ATT_SMEM (BS_OFF + 1024)      // 139264

__global__ __launch_bounds__(256, 1) void attn_kernel(const float* __restrict__ gam,
                                                      const float* __restrict__ bet) {
    extern __shared__ char smc[];
    float* Sb = (float*)(smc + SB_OFF);
    float2* red = (float2*)(smc + RED_OFF);
    float* gs = (float*)(smc + GS_OFF);
    float* bs = (float*)(smc + BS_OFF);
    const unsigned ks_s = (unsigned)__cvta_generic_to_shared(smc);

    const int tid = threadIdx.x;
    const int w = tid >> 5, lane = tid & 31;
    const int qt = lane >> 2, tq = lane & 3;
    const int eh = w & 1;
    const int b = blockIdx.y;
    const int row0 = blockIdx.x * 64 + (w >> 1) * 16;
    const __half* qbb = d_qh + (size_t)b * SS * EE;
    const float C = 0.51006977f;   // log2(e)/sqrt(8)

    gs[tid] = gam[tid];
    bs[tid] = bet[tid];

    unsigned qa[8][4];
    {
        const __half* p0 = qbb + (size_t)(row0 + qt) * EE + eh * 128 + 2 * tq;
        #pragma unroll
        for (int k = 0; k < 8; k++) {
            qa[k][0] = *(const unsigned*)(p0 + 16 * k);
            qa[k][1] = *(const unsigned*)(p0 + 8 * EE + 16 * k);
            qa[k][2] = *(const unsigned*)(p0 + 16 * k + 8);
            qa[k][3] = *(const unsigned*)(p0 + 8 * EE + 16 * k + 8);
        }
    }
    float o[16][4];
    #pragma unroll
    for (int n = 0; n < 16; n++) { o[n][0] = o[n][1] = o[n][2] = o[n][3] = 0.f; }
    float m0 = -1e30f, m1 = -1e30f, l0 = 0.f, l1 = 0.f;

    float* Sw = Sb + w * 16 * SST;
    float* Sp = Sb + (w ^ 1) * 16 * SST;

    const int l7 = lane & 7, l3 = lane >> 3;
    const unsigned qk_off = 2u * (unsigned)(l7 * KP + eh * 128 + 8 * l3);
    const unsigned pv_off = 2u * (unsigned)((l7 + 8 * (l3 & 1)) * KP + eh * 128 + 8 * (l3 >> 1));

    #pragma unroll
    for (int t = 0; t < 2; t++) {
        const uint4* src = (const uint4*)(qbb + (size_t)t * 64 * EE);
        const unsigned dst = ks_s + (unsigned)(t * KS_BYTES);
        #pragma unroll
        for (int p = 0; p < 8; p++) {
            int idx = p * 256 + tid;
            cpasync16(dst + 2u * (unsigned)((idx >> 5) * KP + (idx & 31) * 8), src + idx);
        }
        CP_COMMIT();
    }

    int cur = 0;
    for (int kt = 0; kt < SS / 64; kt++) {
        CP_WAIT1();
        __syncthreads();

        if (kt + 2 < SS / 64) {
            int nxt = cur + 2; if (nxt >= NSTG) nxt -= NSTG;
            const uint4* src = (const uint4*)(qbb + (size_t)(kt + 2) * 64 * EE);
            const unsigned dst = ks_s + (unsigned)(nxt * KS_BYTES);
            #pragma unroll
            for (int p = 0; p < 8; p++) {
                int idx = p * 256 + tid;
                cpasync16(dst + 2u * (unsigned)((idx >> 5) * KP + (idx & 31) * 8), src + idx);
            }
        }
        CP_COMMIT();

        const unsigned ks_cur = ks_s + (unsigned)(cur * KS_BYTES);

        float sc[8][4];
        #pragma unroll
        for (int n = 0; n < 8; n++) { sc[n][0] = sc[n][1] = sc[n][2] = sc[n][3] = 0.f; }
        #pragma unroll
        for (int n = 0; n < 8; n++) {
            unsigned base = ks_cur + qk_off + (unsigned)(n * 8 * KP * 2);
            #pragma unroll
            for (int kk = 0; kk < 4; kk++) {
                unsigned b0, b1, b2, b3;
                ldsm4(b0, b1, b2, b3, base + kk * 64);
                MMA_F16(sc[n], qa[2*kk][0], qa[2*kk][1], qa[2*kk][2], qa[2*kk][3], b0, b1);
                MMA_F16(sc[n], qa[2*kk+1][0], qa[2*kk+1][1], qa[2*kk+1][2], qa[2*kk+1][3], b2, b3);
            }
        }

        #pragma unroll
        for (int n = 0; n < 8; n++) {
            *(float2*)(Sw + qt * SST + n * 8 + 2 * tq)       = make_float2(sc[n][0], sc[n][1]);
            *(float2*)(Sw + (qt + 8) * SST + n * 8 + 2 * tq) = make_float2(sc[n][2], sc[n][3]);
        }
        __syncthreads();
        #pragma unroll
        for (int n = 0; n < 8; n++) {
            float2 p0 = *(const float2*)(Sp + qt * SST + n * 8 + 2 * tq);
            float2 p1 = *(const float2*)(Sp + (qt + 8) * SST + n * 8 + 2 * tq);
            sc[n][0] += p0.x; sc[n][1] += p0.y;
            sc[n][2] += p1.x; sc[n][3] += p1.y;
        }

        float mx0 = sc[0][0], mx1 = sc[0][2];
        #pragma unroll
        for (int n = 0; n < 8; n++) {
            mx0 = fmaxf(mx0, fmaxf(sc[n][0], sc[n][1]));
            mx1 = fmaxf(mx1, fmaxf(sc[n][2], sc[n][3]));
        }
        mx0 = fmaxf(mx0, __shfl_xor_sync(0xffffffffu, mx0, 1));
        mx0 = fmaxf(mx0, __shfl_xor_sync(0xffffffffu, mx0, 2));
        mx1 = fmaxf(mx1, __shfl_xor_sync(0xffffffffu, mx1, 1));
        mx1 = fmaxf(mx1, __shfl_xor_sync(0xffffffffu, mx1, 2));
        float nm0 = fmaxf(m0, mx0), nm1 = fmaxf(m1, mx1);
        if (__ballot_sync(0xffffffffu, (nm0 > m0) | (nm1 > m1))) {
            float c0 = exp2f((m0 - nm0) * C), c1 = exp2f((m1 - nm1) * C);
            l0 *= c0; l1 *= c1;
            #pragma unroll
            for (int n = 0; n < 16; n++) {
                o[n][0] *= c0; o[n][1] *= c0; o[n][2] *= c1; o[n][3] *= c1;
            }
        }
        m0 = nm0; m1 = nm1;

        unsigned pa[4][4];
        float s0 = 0.f, s1 = 0.f;
        #pragma unroll
        for (int kk = 0; kk < 4; kk++) {
            int n0 = 2 * kk, n1 = 2 * kk + 1;
            __half2 h;
            h = __floats2half2_rn(exp2f((sc[n0][0] - m0) * C), exp2f((sc[n0][1] - m0) * C));
            pa[kk][0] = *(unsigned*)&h; s0 += __low2float(h) + __high2float(h);
            h = __floats2half2_rn(exp2f((sc[n0][2] - m1) * C), exp2f((sc[n0][3] - m1) * C));
            pa[kk][1] = *(unsigned*)&h; s1 += __low2float(h) + __high2float(h);
            h = __floats2half2_rn(exp2f((sc[n1][0] - m0) * C), exp2f((sc[n1][1] - m0) * C));
            pa[kk][2] = *(unsigned*)&h; s0 += __low2float(h) + __high2float(h);
            h = __floats2half2_rn(exp2f((sc[n1][2] - m1) * C), exp2f((sc[n1][3] - m1) * C));
            pa[kk][3] = *(unsigned*)&h; s1 += __low2float(h) + __high2float(h);
        }
        s0 += __shfl_xor_sync(0xffffffffu, s0, 1);
        s0 += __shfl_xor_sync(0xffffffffu, s0, 2);
        s1 += __shfl_xor_sync(0xffffffffu, s1, 1);
        s1 += __shfl_xor_sync(0xffffffffu, s1, 2);
        l0 += s0; l1 += s1;

        #pragma unroll
        for (int np = 0; np < 8; np++) {
            unsigned base = ks_cur + pv_off + (unsigned)(np * 32);
            #pragma unroll
            for (int kk = 0; kk < 4; kk++) {
                unsigned b0, b1, b2, b3;
                ldsm4t(b0, b1, b2, b3, base + (unsigned)(kk * 16 * KP * 2));
                MMA_F16(o[2*np],   pa[kk][0], pa[kk][1], pa[kk][2], pa[kk][3], b0, b1);
                MMA_F16(o[2*np+1], pa[kk][0], pa[kk][1], pa[kk][2], pa[kk][3], b2, b3);
            }
        }
        cur = (cur + 1 == NSTG) ? 0 : cur + 1;
    }

    float i0 = 1.f / l0, i1 = 1.f / l1;
    float* xr0 = d_x + ((size_t)b * SS + row0 + qt) * EE;
    float* xr1 = d_x + ((size_t)b * SS + row0 + qt + 8) * EE;
    float sum0 = 0.f, sq0 = 0.f, sum1 = 0.f, sq1 = 0.f;
    #pragma unroll
    for (int n = 0; n < 16; n++) {
        int col = eh * 128 + n * 8 + 2 * tq;
        float2 x0 = *(const float2*)(xr0 + col);
        float2 x1 = *(const float2*)(xr1 + col);
        o[n][0] = o[n][0] * i0 + x0.x;  o[n][1] = o[n][1] * i0 + x0.y;
        o[n][2] = o[n][2] * i1 + x1.x;  o[n][3] = o[n][3] * i1 + x1.y;
        sum0 += o[n][0] + o[n][1]; sq0 += o[n][0] * o[n][0] + o[n][1] * o[n][1];
        sum1 += o[n][2] + o[n][3]; sq1 += o[n][2] * o[n][2] + o[n][3] * o[n][3];
    }
    #pragma unroll
    for (int mask = 1; mask <= 2; mask <<= 1) {
        sum0 += __shfl_xor_sync(0xffffffffu, sum0, mask);
        sq0  += __shfl_xor_sync(0xffffffffu, sq0, mask);
        sum1 += __shfl_xor_sync(0xffffffffu, sum1, mask);
        sq1  += __shfl_xor_sync(0xffffffffu, sq1, mask);
    }
    int pair = w >> 1;
    if (tq == 0) {
        red[(pair * 16 + qt) * 2 + eh]     = make_float2(sum0, sq0);
        red[(pair * 16 + qt + 8) * 2 + eh] = make_float2(sum1, sq1);
    }
    __syncthreads();
    float2 ra = red[(pair * 16 + qt) * 2 + 0], rb = red[(pair * 16 + qt) * 2 + 1];
    float mean0 = (ra.x + rb.x) * (1.f / EE);
    float var0 = (ra.y + rb.y) * (1.f / EE) - mean0 * mean0;
    float rv0 = rsqrtf(var0 + 1e-5f);
    float2 rc = red[(pair * 16 + qt + 8) * 2 + 0], rd = red[(pair * 16 + qt + 8) * 2 + 1];
    float mean1 = (rc.x + rd.x) * (1.f / EE);
    float var1 = (rc.y + rd.y) * (1.f / EE) - mean1 * mean1;
    float rv1 = rsqrtf(var1 + 1e-5f);
    #pragma unroll
    for (int n = 0; n < 16; n++) {
        int col = eh * 128 + n * 8 + 2 * tq;
        float2 gv = *(const float2*)(gs + col);
        float2 bv = *(const float2*)(bs + col);
        *(float2*)(xr0 + col) = make_float2((o[n][0] - mean0) * rv0 * gv.x + bv.x,
                                            (o[n][1] - mean0) * rv0 * gv.y + bv.y);
        *(float2*)(xr1 + col) = make_float2((o[n][2] - mean1) * rv1 * gv.x + bv.x,
                                            (o[n][3] - mean1) * rv1 * gv.y + bv.y);
    }
}

// ---------------- 3. fused FFN + residual LN2 + next-layer qmap ----------------
// CTA: 64 rows x 256 cols; warp = 32 rows x 64 cols; K-tile = 64 (dynamic smem).
// Epilogue: v = f + b2 + x; x = LN(v)*g2+be2 -> d_x; qmap(x) -> d_qh with a
// single full-64-row staging pass through the dead ws region (all warps store
// concurrently; ONE extra barrier).
#define HSP 72    // hs row stride (halves)
#define WSP 264   // ws row stride (halves)
#define XSP 264   // xs row stride (floats), xs reuses/extends ws region
#define FFN_W1_OFF  2304                       // qm float[64][9]
#define FFN_B1_OFF  (FFN_W1_OFF + 2112)        // w1s float[8][66]
#define FFN_B2_OFF  (FFN_B1_OFF + 4096)        // b1s float[1024]
#define FFN_G2_OFF  (FFN_B2_OFF + 1024)        // b2s float[256]
#define FFN_BE2_OFF (FFN_G2_OFF + 1024)        // g2s float[256]
#define FFN_RED_OFF (FFN_BE2_OFF + 1024)       // be2s float[256]
#define FFN_HS_OFF  (FFN_RED_OFF + 2048)       // red float2[64][4]
#define FFN_WS_OFF  (FFN_HS_OFF + 64*HSP*2)    // hs half[64][72]
#define FFN_SMEM    (FFN_WS_OFF + 64*XSP*4)    // max(ws, xs64) => 90432 B

__global__ __launch_bounds__(256, 2) void ffn_kernel(const float* __restrict__ theta,
                                                     const float* __restrict__ W1,
                                                     const float* __restrict__ b1,
                                                     int layer,
                                                     const float* __restrict__ b2,
                                                     const float* __restrict__ gam2,
                                                     const float* __restrict__ bet2,
                                                     const float* __restrict__ phiN) {
    extern __shared__ char fsm[];
    float* qm   = (float*)fsm;                        // [64][9]
    float* w1s  = (float*)(fsm + FFN_W1_OFF);         // [8][66]
    float* b1s  = (float*)(fsm + FFN_B1_OFF);         // [1024]
    float* b2s  = (float*)(fsm + FFN_B2_OFF);         // [256]
    float* g2s  = (float*)(fsm + FFN_G2_OFF);         // [256]
    float* be2s = (float*)(fsm + FFN_BE2_OFF);        // [256]
    float2* redp = (float2*)(fsm + FFN_RED_OFF);      // [64][4]
    __half* hs  = (__half*)(fsm + FFN_HS_OFF);        // [64][HSP]
    __half* ws  = (__half*)(fsm + FFN_WS_OFF);        // [64][WSP]
    float*  xs  = (float*)(fsm + FFN_WS_OFF);         // [64][XSP] (reuse, larger)

    const __half* __restrict__ W2h = d_w2h + (size_t)layer * FF * EE;
    const int t = threadIdx.x, w = t >> 5, lane = t & 31;
    const int qt = lane >> 2, tq = lane & 3;
    const int l7 = lane & 7, l3 = lane >> 3;
    const int wm = w >> 2, wn = w & 3;
    const int rowBase = blockIdx.x * 64;
    const unsigned hs_s = (unsigned)__cvta_generic_to_shared(hs);
    const unsigned ws_s = (unsigned)__cvta_generic_to_shared(ws);

    b2s[t] = b2[t];
    g2s[t] = gam2[t];
    be2s[t] = bet2[t];
    #pragma unroll
    for (int p = 0; p < 4; p++) b1s[t + p * 256] = b1[t + p * 256];
    #pragma unroll
    for (int i = 0; i < 2; i++) {
        int idx = t * 2 + i;
        int r = idx >> 3, j = idx & 7;
        qm[r * 9 + j] = cosf(d_x[(size_t)(rowBase + r) * EE + j]) * cosf(theta[j]);
    }

    float c[2][8][4];
    #pragma unroll
    for (int mt = 0; mt < 2; mt++)
        #pragma unroll
        for (int nt = 0; nt < 8; nt++)
            c[mt][nt][0] = c[mt][nt][1] = c[mt][nt][2] = c[mt][nt][3] = 0.f;

    for (int kt = 0; kt < FF / 64; kt++) {
        int k0g = kt * 64;
        __syncthreads();
        {   // W1 tile 8x64
            #pragma unroll
            for (int p = 0; p < 2; p++) {
                int idx = p * 256 + t;
                w1s[(idx >> 6) * 66 + (idx & 63)] = W1[(idx >> 6) * FF + k0g + (idx & 63)];
            }
        }
        {   // W2 fp16 tile 64x256
            const uint4* w4 = (const uint4*)(W2h + (size_t)k0g * EE);
            #pragma unroll
            for (int p = 0; p < 8; p++) {
                int idx = p * 256 + t;
                *(uint4*)(&ws[(idx >> 5) * WSP + (idx & 31) * 8]) = w4[idx];
            }
        }
        __syncthreads();
        {   // hidden tile 64x64 via fused ffn1 (fp32 math -> fp16 store)
            int r = t & 63, cg = (t >> 6) * 16;
            #pragma unroll
            for (int i = 0; i < 16; i++) {
                int cc = cg + i;
                float h = b1s[k0g + cc];
                #pragma unroll
                for (int j = 0; j < 8; j++) h += qm[r * 9 + j] * w1s[j * 66 + cc];
                hs[r * HSP + cc] = __float2half(fmaxf(h, 0.f));
            }
        }
        __syncthreads();
        #pragma unroll
        for (int ks = 0; ks < 4; ks++) {
            unsigned a[2][4];
            #pragma unroll
            for (int mt = 0; mt < 2; mt++) {
                int mrow = wm * 32 + mt * 16;
                unsigned addr = hs_s + 2u * (unsigned)((mrow + l7 + 8 * (l3 & 1)) * HSP +
                                                       ks * 16 + 8 * (l3 >> 1));
                ldsm4(a[mt][0], a[mt][1], a[mt][2], a[mt][3], addr);
            }
            #pragma unroll
            for (int ng = 0; ng < 4; ng++) {
                int n0 = wn * 64 + ng * 16;
                unsigned baddr = ws_s + 2u * (unsigned)((ks * 16 + l7 + 8 * (l3 & 1)) * WSP +
                                                        n0 + 8 * (l3 >> 1));
                unsigned b0, b1r, b2r, b3;
                ldsm4t(b0, b1r, b2r, b3, baddr);
                MMA_F16(c[0][2*ng],   a[0][0], a[0][1], a[0][2], a[0][3], b0, b1r);
                MMA_F16(c[0][2*ng+1], a[0][0], a[0][1], a[0][2], a[0][3], b2r, b3);
                MMA_F16(c[1][2*ng],   a[1][0], a[1][1], a[1][2], a[1][3], b0, b1r);
                MMA_F16(c[1][2*ng+1], a[1][0], a[1][1], a[1][2], a[1][3], b2r, b3);
            }
        }
    }

    // ---- fused epilogue: v = f + b2 + x ; x = LN(v) ; write d_x ; qmap ----
    float sum[2][2] = {{0.f, 0.f}, {0.f, 0.f}};
    float sq[2][2]  = {{0.f, 0.f}, {0.f, 0.f}};
    #pragma unroll
    for (int mt = 0; mt < 2; mt++) {
        int gr = rowBase + wm * 32 + mt * 16;
        #pragma unroll
        for (int nt = 0; nt < 8; nt++) {
            int col = wn * 64 + nt * 8 + 2 * tq;
            float2 x0 = *(const float2*)(d_x + (size_t)(gr + qt) * EE + col);
            float2 x1 = *(const float2*)(d_x + (size_t)(gr + qt + 8) * EE + col);
            float bb0 = b2s[col], bb1 = b2s[col + 1];
            c[mt][nt][0] += bb0 + x0.x;  c[mt][nt][1] += bb1 + x0.y;
            c[mt][nt][2] += bb0 + x1.x;  c[mt][nt][3] += bb1 + x1.y;
            sum[mt][0] += c[mt][nt][0] + c[mt][nt][1];
            sq[mt][0]  += c[mt][nt][0] * c[mt][nt][0] + c[mt][nt][1] * c[mt][nt][1];
            sum[mt][1] += c[mt][nt][2] + c[mt][nt][3];
            sq[mt][1]  += c[mt][nt][2] * c[mt][nt][2] + c[mt][nt][3] * c[mt][nt][3];
        }
    }
    #pragma unroll
    for (int mask = 1; mask <= 2; mask <<= 1) {
        #pragma unroll
        for (int mt = 0; mt < 2; mt++) {
            #pragma unroll
            for (int rh = 0; rh < 2; rh++) {
                sum[mt][rh] += __shfl_xor_sync(0xffffffffu, sum[mt][rh], mask);
                sq[mt][rh]  += __shfl_xor_sync(0xffffffffu, sq[mt][rh], mask);
            }
        }
    }
    if (tq == 0) {
        #pragma unroll
        for (int mt = 0; mt < 2; mt++)
            #pragma unroll
            for (int rh = 0; rh < 2; rh++)
                redp[(wm * 32 + mt * 16 + qt + rh * 8) * 4 + wn] =
                    make_float2(sum[mt][rh], sq[mt][rh]);
    }
    __syncthreads();   // also orders the last ws ldsm reads before xs writes below
    float mean[2][2], rv[2][2];
    #pragma unroll
    for (int mt = 0; mt < 2; mt++) {
        #pragma unroll
        for (int rh = 0; rh < 2; rh++) {
            int row = wm * 32 + mt * 16 + qt + rh * 8;
            float2 r0 = redp[row * 4 + 0], r1 = redp[row * 4 + 1];
            float2 r2 = redp[row * 4 + 2], r3 = redp[row * 4 + 3];
            float s = r0.x + r1.x + r2.x + r3.x;
            float q = r0.y + r1.y + r2.y + r3.y;
            float mn = s * (1.f / EE);
            mean[mt][rh] = mn;
            rv[mt][rh] = rsqrtf(q * (1.f / EE) - mn * mn + 1e-5f);
        }
    }
    // apply LN in-register + write d_x (+ stage all 64 rows to xs if qmap needed)
    #pragma unroll
    for (int mt = 0; mt < 2; mt++) {
        int gr = rowBase + wm * 32 + mt * 16;
        int lr = wm * 32 + mt * 16;
        #pragma unroll
        for (int nt = 0; nt < 8; nt++) {
            int col = wn * 64 + nt * 8 + 2 * tq;
            float g0 = g2s[col], g1v = g2s[col + 1];
            float e0 = be2s[col], e1 = be2s[col + 1];
            c[mt][nt][0] = (c[mt][nt][0] - mean[mt][0]) * rv[mt][0] * g0 + e0;
            c[mt][nt][1] = (c[mt][nt][1] - mean[mt][0]) * rv[mt][0] * g1v + e1;
            c[mt][nt][2] = (c[mt][nt][2] - mean[mt][1]) * rv[mt][1] * g0 + e0;
            c[mt][nt][3] = (c[mt][nt][3] - mean[mt][1]) * rv[mt][1] * g1v + e1;
            *(float2*)(d_x + (size_t)(gr + qt) * EE + col) =
                make_float2(c[mt][nt][0], c[mt][nt][1]);
            *(float2*)(d_x + (size_t)(gr + qt + 8) * EE + col) =
                make_float2(c[mt][nt][2], c[mt][nt][3]);
            if (phiN) {
                *(float2*)(xs + (lr + qt) * XSP + col) =
                    make_float2(c[mt][nt][0], c[mt][nt][1]);
                *(float2*)(xs + (lr + qt + 8) * XSP + col) =
                    make_float2(c[mt][nt][2], c[mt][nt][3]);
            }
        }
    }
    // next-layer q: all 64 rows staged; 2048 (row, head) tasks over 256 threads
    if (phiN) {
        __syncthreads();
        #pragma unroll
        for (int k2 = 0; k2 < 8; k2++) {
            int task = t + k2 * 256;          // 2048 = 64 rows x 32 heads
            int row = task >> 5, head = task & 31;
            const float* xp = xs + row * XSP + head * 8;
            float v8[8];
            #pragma unroll
            for (int i = 0; i < 8; i++) v8[i] = xp[i];
            float out[8];
            qmap8(v8, phiN, out);
            store_q8(d_qh + (size_t)(rowBase + row) * EE + head * 8, out);
        }
    }
}

// ---------------- 4a. head partial sums: 64 rows per CTA ----------------
__global__ void psum_kernel() {
    int b = blockIdx.y, chunk = blockIdx.x;   // (32, 8)
    int e = threadIdx.x;
    const float* base = d_x + ((size_t)b * SS + chunk * 64) * EE + e;
    float s = 0.f;
    #pragma unroll 8
    for (int i = 0; i < 64; i++) s += base[(size_t)i * EE];
    d_part[((size_t)b * 32 + chunk) * EE + e] = s;
}

// ---------------- 4b. final mean + classifier head ----------------
__global__ void head_kernel(const float* __restrict__ Wc, const float* __restrict__ bc,
                            float* __restrict__ out) {
    __shared__ float mean[EE];
    int b = blockIdx.x;
    int e = threadIdx.x;
    const float* p = d_part + (size_t)b * 32 * EE + e;
    float s = 0.f;
    #pragma unroll
    for (int i = 0; i < 32; i++) s += p[i * EE];
    mean[e] = s * (1.f / SS);
    __syncthreads();
    if (e < NC) {
        float acc = bc[e];
        for (int ee = 0; ee < EE; ee++)
            acc += mean[ee] * Wc[ee * NC + e];
        out[b * NC + e] = acc;
    }
}

// ---------------- launch ----------------
extern "C" void kernel_launch(void* const* d_in, const int* in_sizes, int n_in,
                              void* d_out, int out_size) {
    const int*   tok   = (const int*)d_in[0];
    const float* emb   = (const float*)d_in[1];
    const float* phi   = (const float*)d_in[2];
    const float* theta = (const float*)d_in[3];
    const float* W1    = (const float*)d_in[4];
    const float* b1    = (const float*)d_in[5];
    const float* W2    = (const float*)d_in[6];
    const float* b2    = (const float*)d_in[7];
    const float* g1    = (const float*)d_in[8];
    const float* be1   = (const float*)d_in[9];
    const float* g2    = (const float*)d_in[10];
    const float* be2   = (const float*)d_in[11];
    const float* Wc    = (const float*)d_in[12];
    const float* bc    = (const float*)d_in[13];
    float* out = (float*)d_out;

    cudaFuncSetAttribute(attn_kernel, cudaFuncAttributeMaxDynamicSharedMemorySize, ATT_SMEM);
    cudaFuncSetAttribute(ffn_kernel, cudaFuncAttributeMaxDynamicSharedMemorySize, FFN_SMEM);

    w2cvt_kernel<<<LL * FF * EE / 4 / 256, 256>>>(W2);
    embed_q_kernel<<<ROWS * 32 / 256, 256>>>(tok, emb, phi);
    for (int l = 0; l < LL; l++) {
        attn_kernel<<<dim3(SS / 64, BB), 256, ATT_SMEM>>>(g1 + l * EE, be1 + l * EE);
        ffn_kernel<<<ROWS / 64, 256, FFN_SMEM>>>(theta + l * NQ, W1 + (size_t)l * NQ * FF,
                                                 b1 + l * FF, l, b2 + l * EE,
                                                 g2 + l * EE, be2 + l * EE,
                                                 (l < LL - 1) ? (phi + (l + 1) * NQ) : nullptr);
    }
    psum_kernel<<<dim3(32, BB), 256>>>();
    head_kernel<<<BB, 256>>>(Wc, bc, out);
}

// round 15
// speedup vs baseline: 1.0148x; 1.0005x over previous
#include <cuda_runtime.h>
#include <cuda_fp16.h>
#include <math.h>

#define BB 8
#define SS 2048
#define EE 256
#define LL 4
#define FF 1024
#define NQ 8
#define NC 10
#define ROWS (BB*SS)   // 16384

// ---------------- scratch (static device arrays; no allocation) ----------------
__device__ float d_x[ROWS*EE];            // activations  (16 MB)
__device__ __half d_qh[ROWS*EE];          // quantum q, fp16 (8 MB)
__device__ float d_a[ROWS*EE];            // ffn out (16 MB)
__device__ __half d_w2h[LL*FF*EE];        // fp16 copy of W2 (4 MB)
__device__ float d_part[BB*32*EE];        // head partial sums (256 KB)

#define MMA_F16(d, a0, a1, a2, a3, b0, b1)                                    \
    asm volatile(                                                             \
        "mma.sync.aligned.m16n8k16.row.col.f32.f16.f16.f32 "                  \
        "{%0,%1,%2,%3}, {%4,%5,%6,%7}, {%8,%9}, {%0,%1,%2,%3};"               \
        : "+f"(d[0]), "+f"(d[1]), "+f"(d[2]), "+f"(d[3])                      \
        : "r"(a0), "r"(a1), "r"(a2), "r"(a3), "r"(b0), "r"(b1))

__device__ __forceinline__ void ldsm4(unsigned& r0, unsigned& r1, unsigned& r2,
                                      unsigned& r3, unsigned a) {
    asm volatile("ldmatrix.sync.aligned.m8n8.x4.shared.b16 {%0,%1,%2,%3}, [%4];"
                 : "=r"(r0), "=r"(r1), "=r"(r2), "=r"(r3) : "r"(a));
}
__device__ __forceinline__ void ldsm4t(unsigned& r0, unsigned& r1, unsigned& r2,
                                       unsigned& r3, unsigned a) {
    asm volatile("ldmatrix.sync.aligned.m8n8.x4.trans.shared.b16 {%0,%1,%2,%3}, [%4];"
                 : "=r"(r0), "=r"(r1), "=r"(r2), "=r"(r3) : "r"(a));
}
__device__ __forceinline__ void cpasync16(unsigned dst, const void* src) {
    asm volatile("cp.async.cg.shared.global [%0], [%1], 16;" :: "r"(dst), "l"(src));
}
#define CP_COMMIT() asm volatile("cp.async.commit_group;" ::: "memory")
#define CP_WAIT1()  asm volatile("cp.async.wait_group 1;" ::: "memory")

// q-map: c_j = cos(v_j + phi_j); q_0 = prod_{j>=1} c_j; q_i = prod_{j<=i} c_j
__device__ __forceinline__ void qmap8(const float* v, const float* phi, float* out) {
    float c[8];
    #pragma unroll
    for (int i = 0; i < 8; i++) c[i] = cosf(v[i] + phi[i]);
    float t = c[1];
    #pragma unroll
    for (int j = 2; j < 8; j++) t *= c[j];
    out[0] = t;
    float pref = c[0];
    #pragma unroll
    for (int i = 1; i < 8; i++) { pref *= c[i]; out[i] = pref; }
}
__device__ __forceinline__ void store_q8(__half* qp, const float* out) {
    __half2* q2 = (__half2*)qp;
    q2[0] = __floats2half2_rn(out[0], out[1]);
    q2[1] = __floats2half2_rn(out[2], out[3]);
    q2[2] = __floats2half2_rn(out[4], out[5]);
    q2[3] = __floats2half2_rn(out[6], out[7]);
}

// ---------------- 0. W2 -> fp16 copy ----------------
__global__ void w2cvt_kernel(const float* __restrict__ W2) {
    int i = blockIdx.x * blockDim.x + threadIdx.x;
    float4 v = ((const float4*)W2)[i];
    __half2* dst = (__half2*)d_w2h;
    dst[2 * i]     = __floats2half2_rn(v.x, v.y);
    dst[2 * i + 1] = __floats2half2_rn(v.z, v.w);
}

// ---------------- 1. embedding + PE + layer-0 q (fused) ----------------
__global__ void embed_q_kernel(const int* __restrict__ tok, const float* __restrict__ emb,
                               const float* __restrict__ phi) {
    int g = blockIdx.x * blockDim.x + threadIdx.x;   // ROWS*32: (row, head)
    int row = g >> 5, h = g & 31;
    int s = row & (SS - 1);
    int base = row * EE + h * 8;
    const float4* er = (const float4*)(emb + (size_t)tok[row] * EE + h * 8);
    float4 e0 = er[0], e1 = er[1];
    float v[8] = {e0.x, e0.y, e0.z, e0.w, e1.x, e1.y, e1.z, e1.w};
    #pragma unroll
    for (int i = 0; i < 8; i++) {
        int e = h * 8 + i;
        float freq = expf((float)(e & ~1) * (-9.210340371976184f / 256.0f));
        float ang = (float)s * freq;
        v[i] += (e & 1) ? cosf(ang) : sinf(ang);
    }
    *(float4*)(d_x + base)     = make_float4(v[0], v[1], v[2], v[3]);
    *(float4*)(d_x + base + 4) = make_float4(v[4], v[5], v[6], v[7]);
    float out[8];
    qmap8(v, phi, out);
    store_q8(d_qh + base, out);
}

// ---------------- 2. fp16 flash attention + fused residual LayerNorm ----------------
// (identical to the R12/R14 passing version)
#define NSTG 3
#define KP 264                        // Ks row stride (halves)
#define SST 68                        // Sb row stride (fp32)
#define KS_BYTES (64 * KP * 2)        // 33792 per stage
#define SB_OFF (NSTG * KS_BYTES)      // 101376
#define SB_BYTES (8 * 16 * SST * 4)   // 34816
#define RED_OFF (SB_OFF + SB_BYTES)   // 136192
#define GS_OFF (RED_OFF + 1024)
#define BS_OFF (GS_OFF + 1024)
#define ATT_SMEM (BS_OFF + 1024)      // 139264

__global__ __launch_bounds__(256, 1) void attn_kernel(const float* __restrict__ gam,
                                                      const float* __restrict__ bet) {
    extern __shared__ char smc[];
    float* Sb = (float*)(smc + SB_OFF);
    float2* red = (float2*)(smc + RED_OFF);
    float* gs = (float*)(smc + GS_OFF);
    float* bs = (float*)(smc + BS_OFF);
    const unsigned ks_s = (unsigned)__cvta_generic_to_shared(smc);

    const int tid = threadIdx.x;
    const int w = tid >> 5, lane = tid & 31;
    const int qt = lane >> 2, tq = lane & 3;
    const int eh = w & 1;
    const int b = blockIdx.y;
    const int row0 = blockIdx.x * 64 + (w >> 1) * 16;
    const __half* qbb = d_qh + (size_t)b * SS * EE;
    const float C = 0.51006977f;   // log2(e)/sqrt(8)

    gs[tid] = gam[tid];
    bs[tid] = bet[tid];

    unsigned qa[8][4];
    {
        const __half* p0 = qbb + (size_t)(row0 + qt) * EE + eh * 128 + 2 * tq;
        #pragma unroll
        for (int k = 0; k < 8; k++) {
            qa[k][0] = *(const unsigned*)(p0 + 16 * k);
            qa[k][1] = *(const unsigned*)(p0 + 8 * EE + 16 * k);
            qa[k][2] = *(const unsigned*)(p0 + 16 * k + 8);
            qa[k][3] = *(const unsigned*)(p0 + 8 * EE + 16 * k + 8);
        }
    }
    float o[16][4];
    #pragma unroll
    for (int n = 0; n < 16; n++) { o[n][0] = o[n][1] = o[n][2] = o[n][3] = 0.f; }
    float m0 = -1e30f, m1 = -1e30f, l0 = 0.f, l1 = 0.f;

    float* Sw = Sb + w * 16 * SST;
    float* Sp = Sb + (w ^ 1) * 16 * SST;

    const int l7 = lane & 7, l3 = lane >> 3;
    const unsigned qk_off = 2u * (unsigned)(l7 * KP + eh * 128 + 8 * l3);
    const unsigned pv_off = 2u * (unsigned)((l7 + 8 * (l3 & 1)) * KP + eh * 128 + 8 * (l3 >> 1));

    #pragma unroll
    for (int t = 0; t < 2; t++) {
        const uint4* src = (const uint4*)(qbb + (size_t)t * 64 * EE);
        const unsigned dst = ks_s + (unsigned)(t * KS_BYTES);
        #pragma unroll
        for (int p = 0; p < 8; p++) {
            int idx = p * 256 + tid;
            cpasync16(dst + 2u * (unsigned)((idx >> 5) * KP + (idx & 31) * 8), src + idx);
        }
        CP_COMMIT();
    }

    int cur = 0;
    for (int kt = 0; kt < SS / 64; kt++) {
        CP_WAIT1();
        __syncthreads();

        if (kt + 2 < SS / 64) {
            int nxt = cur + 2; if (nxt >= NSTG) nxt -= NSTG;
            const uint4* src = (const uint4*)(qbb + (size_t)(kt + 2) * 64 * EE);
            const unsigned dst = ks_s + (unsigned)(nxt * KS_BYTES);
            #pragma unroll
            for (int p = 0; p < 8; p++) {
                int idx = p * 256 + tid;
                cpasync16(dst + 2u * (unsigned)((idx >> 5) * KP + (idx & 31) * 8), src + idx);
            }
        }
        CP_COMMIT();

        const unsigned ks_cur = ks_s + (unsigned)(cur * KS_BYTES);

        float sc[8][4];
        #pragma unroll
        for (int n = 0; n < 8; n++) { sc[n][0] = sc[n][1] = sc[n][2] = sc[n][3] = 0.f; }
        #pragma unroll
        for (int n = 0; n < 8; n++) {
            unsigned base = ks_cur + qk_off + (unsigned)(n * 8 * KP * 2);
            #pragma unroll
            for (int kk = 0; kk < 4; kk++) {
                unsigned b0, b1, b2, b3;
                ldsm4(b0, b1, b2, b3, base + kk * 64);
                MMA_F16(sc[n], qa[2*kk][0], qa[2*kk][1], qa[2*kk][2], qa[2*kk][3], b0, b1);
                MMA_F16(sc[n], qa[2*kk+1][0], qa[2*kk+1][1], qa[2*kk+1][2], qa[2*kk+1][3], b2, b3);
            }
        }

        #pragma unroll
        for (int n = 0; n < 8; n++) {
            *(float2*)(Sw + qt * SST + n * 8 + 2 * tq)       = make_float2(sc[n][0], sc[n][1]);
            *(float2*)(Sw + (qt + 8) * SST + n * 8 + 2 * tq) = make_float2(sc[n][2], sc[n][3]);
        }
        __syncthreads();
        #pragma unroll
        for (int n = 0; n < 8; n++) {
            float2 p0 = *(const float2*)(Sp + qt * SST + n * 8 + 2 * tq);
            float2 p1 = *(const float2*)(Sp + (qt + 8) * SST + n * 8 + 2 * tq);
            sc[n][0] += p0.x; sc[n][1] += p0.y;
            sc[n][2] += p1.x; sc[n][3] += p1.y;
        }

        float mx0 = sc[0][0], mx1 = sc[0][2];
        #pragma unroll
        for (int n = 0; n < 8; n++) {
            mx0 = fmaxf(mx0, fmaxf(sc[n][0], sc[n][1]));
            mx1 = fmaxf(mx1, fmaxf(sc[n][2], sc[n][3]));
        }
        mx0 = fmaxf(mx0, __shfl_xor_sync(0xffffffffu, mx0, 1));
        mx0 = fmaxf(mx0, __shfl_xor_sync(0xffffffffu, mx0, 2));
        mx1 = fmaxf(mx1, __shfl_xor_sync(0xffffffffu, mx1, 1));
        mx1 = fmaxf(mx1, __shfl_xor_sync(0xffffffffu, mx1, 2));
        float nm0 = fmaxf(m0, mx0), nm1 = fmaxf(m1, mx1);
        if (__ballot_sync(0xffffffffu, (nm0 > m0) | (nm1 > m1))) {
            float c0 = exp2f((m0 - nm0) * C), c1 = exp2f((m1 - nm1) * C);
            l0 *= c0; l1 *= c1;
            #pragma unroll
            for (int n = 0; n < 16; n++) {
                o[n][0] *= c0; o[n][1] *= c0; o[n][2] *= c1; o[n][3] *= c1;
            }
        }
        m0 = nm0; m1 = nm1;

        unsigned pa[4][4];
        float s0 = 0.f, s1 = 0.f;
        #pragma unroll
        for (int kk = 0; kk < 4; kk++) {
            int n0 = 2 * kk, n1 = 2 * kk + 1;
            __half2 h;
            h = __floats2half2_rn(exp2f((sc[n0][0] - m0) * C), exp2f((sc[n0][1] - m0) * C));
            pa[kk][0] = *(unsigned*)&h; s0 += __low2float(h) + __high2float(h);
            h = __floats2half2_rn(exp2f((sc[n0][2] - m1) * C), exp2f((sc[n0][3] - m1) * C));
            pa[kk][1] = *(unsigned*)&h; s1 += __low2float(h) + __high2float(h);
            h = __floats2half2_rn(exp2f((sc[n1][0] - m0) * C), exp2f((sc[n1][1] - m0) * C));
            pa[kk][2] = *(unsigned*)&h; s0 += __low2float(h) + __high2float(h);
            h = __floats2half2_rn(exp2f((sc[n1][2] - m1) * C), exp2f((sc[n1][3] - m1) * C));
            pa[kk][3] = *(unsigned*)&h; s1 += __low2float(h) + __high2float(h);
        }
        s0 += __shfl_xor_sync(0xffffffffu, s0, 1);
        s0 += __shfl_xor_sync(0xffffffffu, s0, 2);
        s1 += __shfl_xor_sync(0xffffffffu, s1, 1);
        s1 += __shfl_xor_sync(0xffffffffu, s1, 2);
        l0 += s0; l1 += s1;

        #pragma unroll
        for (int np = 0; np < 8; np++) {
            unsigned base = ks_cur + pv_off + (unsigned)(np * 32);
            #pragma unroll
            for (int kk = 0; kk < 4; kk++) {
                unsigned b0, b1, b2, b3;
                ldsm4t(b0, b1, b2, b3, base + (unsigned)(kk * 16 * KP * 2));
                MMA_F16(o[2*np],   pa[kk][0], pa[kk][1], pa[kk][2], pa[kk][3], b0, b1);
                MMA_F16(o[2*np+1], pa[kk][0], pa[kk][1], pa[kk][2], pa[kk][3], b2, b3);
            }
        }
        cur = (cur + 1 == NSTG) ? 0 : cur + 1;
    }

    float i0 = 1.f / l0, i1 = 1.f / l1;
    float* xr0 = d_x + ((size_t)b * SS + row0 + qt) * EE;
    float* xr1 = d_x + ((size_t)b * SS + row0 + qt + 8) * EE;
    float sum0 = 0.f, sq0 = 0.f, sum1 = 0.f, sq1 = 0.f;
    #pragma unroll
    for (int n = 0; n < 16; n++) {
        int col = eh * 128 + n * 8 + 2 * tq;
        float2 x0 = *(const float2*)(xr0 + col);
        float2 x1 = *(const float2*)(xr1 + col);
        o[n][0] = o[n][0] * i0 + x0.x;  o[n][1] = o[n][1] * i0 + x0.y;
        o[n][2] = o[n][2] * i1 + x1.x;  o[n][3] = o[n][3] * i1 + x1.y;
        sum0 += o[n][0] + o[n][1]; sq0 += o[n][0] * o[n][0] + o[n][1] * o[n][1];
        sum1 += o[n][2] + o[n][3]; sq1 += o[n][2] * o[n][2] + o[n][3] * o[n][3];
    }
    #pragma unroll
    for (int mask = 1; mask <= 2; mask <<= 1) {
        sum0 += __shfl_xor_sync(0xffffffffu, sum0, mask);
        sq0  += __shfl_xor_sync(0xffffffffu, sq0, mask);
        sum1 += __shfl_xor_sync(0xffffffffu, sum1, mask);
        sq1  += __shfl_xor_sync(0xffffffffu, sq1, mask);
    }
    int pair = w >> 1;
    if (tq == 0) {
        red[(pair * 16 + qt) * 2 + eh]     = make_float2(sum0, sq0);
        red[(pair * 16 + qt + 8) * 2 + eh] = make_float2(sum1, sq1);
    }
    __syncthreads();
    float2 ra = red[(pair * 16 + qt) * 2 + 0], rb = red[(pair * 16 + qt) * 2 + 1];
    float mean0 = (ra.x + rb.x) * (1.f / EE);
    float var0 = (ra.y + rb.y) * (1.f / EE) - mean0 * mean0;
    float rv0 = rsqrtf(var0 + 1e-5f);
    float2 rc = red[(pair * 16 + qt + 8) * 2 + 0], rd = red[(pair * 16 + qt + 8) * 2 + 1];
    float mean1 = (rc.x + rd.x) * (1.f / EE);
    float var1 = (rc.y + rd.y) * (1.f / EE) - mean1 * mean1;
    float rv1 = rsqrtf(var1 + 1e-5f);
    #pragma unroll
    for (int n = 0; n < 16; n++) {
        int col = eh * 128 + n * 8 + 2 * tq;
        float2 gv = *(const float2*)(gs + col);
        float2 bv = *(const float2*)(bs + col);
        *(float2*)(xr0 + col) = make_float2((o[n][0] - mean0) * rv0 * gv.x + bv.x,
                                            (o[n][1] - mean0) * rv0 * gv.y + bv.y);
        *(float2*)(xr1 + col) = make_float2((o[n][2] - mean1) * rv1 * gv.x + bv.x,
                                            (o[n][3] - mean1) * rv1 * gv.y + bv.y);
    }
}

// ---------------- 3. x = LayerNorm(x + a), optional fused q for next layer ----------------
__global__ void addln_kernel(const float* __restrict__ gam, const float* __restrict__ bet,
                             const float* __restrict__ phi) {
    int warp = threadIdx.x >> 5, lane = threadIdx.x & 31;
    int row = blockIdx.x * 8 + warp;
    int base = row * EE + lane * 8;
    float4 x0 = *(float4*)(d_x + base), x1 = *(float4*)(d_x + base + 4);
    float4 f0 = *(const float4*)(d_a + base), f1 = *(const float4*)(d_a + base + 4);
    float v[8] = {x0.x + f0.x, x0.y + f0.y, x0.z + f0.z, x0.w + f0.w,
                  x1.x + f1.x, x1.y + f1.y, x1.z + f1.z, x1.w + f1.w};
    float sum = 0.f, sq = 0.f;
    #pragma unroll
    for (int i = 0; i < 8; i++) { sum += v[i]; sq += v[i] * v[i]; }
    #pragma unroll
    for (int mask = 16; mask >= 1; mask >>= 1) {
        sum += __shfl_xor_sync(0xffffffffu, sum, mask);
        sq  += __shfl_xor_sync(0xffffffffu, sq, mask);
    }
    float mean = sum * (1.f / EE);
    float var = sq * (1.f / EE) - mean * mean;
    float inv = rsqrtf(var + 1e-5f);
    float4 g0 = *(const float4*)(gam + lane * 8), g1v = *(const float4*)(gam + lane * 8 + 4);
    float4 b0 = *(const float4*)(bet + lane * 8), b1v = *(const float4*)(bet + lane * 8 + 4);
    float gv[8] = {g0.x, g0.y, g0.z, g0.w, g1v.x, g1v.y, g1v.z, g1v.w};
    float bv[8] = {b0.x, b0.y, b0.z, b0.w, b1v.x, b1v.y, b1v.z, b1v.w};
    #pragma unroll
    for (int i = 0; i < 8; i++) v[i] = (v[i] - mean) * inv * gv[i] + bv[i];
    *(float4*)(d_x + base)     = make_float4(v[0], v[1], v[2], v[3]);
    *(float4*)(d_x + base + 4) = make_float4(v[4], v[5], v[6], v[7]);
    if (phi) {
        float out[8];
        qmap8(v, phi, out);
        store_q8(d_qh + base, out);
    }
}

// ---------------- 4. fused FFN on tensor cores (fp16 mma, fp32 accum) ----------------
// CTA: 64 rows x 256 cols; warp = 32 rows x 64 cols; K-tile = 64 (dynamic smem)
// (identical to the R12 passing version, measured 62.1 us/layer)
#define HSP 72    // hs row stride (halves)
#define WSP 264   // ws row stride (halves)
#define FFN_W1_OFF 2304                      // qm float[64][9]
#define FFN_B1_OFF (FFN_W1_OFF + 2112)       // w1s float[8][66]
#define FFN_B2_OFF (FFN_B1_OFF + 4096)       // b1s float[1024]
#define FFN_HS_OFF (FFN_B2_OFF + 1024)       // b2s float[256]
#define FFN_WS_OFF (FFN_HS_OFF + 64*HSP*2)   // hs half[64][72]
#define FFN_SMEM   (FFN_WS_OFF + 64*WSP*2)   // ws half[64][264]  => 52544 B

__global__ __launch_bounds__(256, 2) void ffn_kernel(const float* __restrict__ theta,
                                                     const float* __restrict__ W1,
                                                     const float* __restrict__ b1,
                                                     int layer,
                                                     const float* __restrict__ b2) {
    extern __shared__ char fsm[];
    float* qm  = (float*)fsm;                       // [64][9]
    float* w1s = (float*)(fsm + FFN_W1_OFF);        // [8][66]
    float* b1s = (float*)(fsm + FFN_B1_OFF);        // [1024]
    float* b2s = (float*)(fsm + FFN_B2_OFF);        // [256]
    __half* hs = (__half*)(fsm + FFN_HS_OFF);       // [64][HSP]
    __half* ws = (__half*)(fsm + FFN_WS_OFF);       // [64][WSP]

    const __half* __restrict__ W2h = d_w2h + (size_t)layer * FF * EE;
    const int t = threadIdx.x, w = t >> 5, lane = t & 31;
    const int qt = lane >> 2, tq = lane & 3;
    const int l7 = lane & 7, l3 = lane >> 3;
    const int wm = w >> 2, wn = w & 3;
    const int rowBase = blockIdx.x * 64;
    const unsigned hs_s = (unsigned)__cvta_generic_to_shared(hs);
    const unsigned ws_s = (unsigned)__cvta_generic_to_shared(ws);

    b2s[t] = b2[t];
    #pragma unroll
    for (int p = 0; p < 4; p++) b1s[t + p * 256] = b1[t + p * 256];
    #pragma unroll
    for (int i = 0; i < 2; i++) {
        int idx = t * 2 + i;
        int r = idx >> 3, j = idx & 7;
        qm[r * 9 + j] = cosf(d_x[(size_t)(rowBase + r) * EE + j]) * cosf(theta[j]);
    }

    float c[2][8][4];
    #pragma unroll
    for (int mt = 0; mt < 2; mt++)
        #pragma unroll
        for (int nt = 0; nt < 8; nt++)
            c[mt][nt][0] = c[mt][nt][1] = c[mt][nt][2] = c[mt][nt][3] = 0.f;

    for (int kt = 0; kt < FF / 64; kt++) {
        int k0g = kt * 64;
        __syncthreads();
        {   // W1 tile 8x64
            #pragma unroll
            for (int p = 0; p < 2; p++) {
                int idx = p * 256 + t;
                w1s[(idx >> 6) * 66 + (idx & 63)] = W1[(idx >> 6) * FF + k0g + (idx & 63)];
            }
        }
        {   // W2 fp16 tile 64x256
            const uint4* w4 = (const uint4*)(W2h + (size_t)k0g * EE);
            #pragma unroll
            for (int p = 0; p < 8; p++) {
                int idx = p * 256 + t;
                *(uint4*)(&ws[(idx >> 5) * WSP + (idx & 31) * 8]) = w4[idx];
            }
        }
        __syncthreads();
        {   // hidden tile 64x64 via fused ffn1 (fp32 math -> fp16 store)
            int r = t & 63, cg = (t >> 6) * 16;
            #pragma unroll
            for (int i = 0; i < 16; i++) {
                int cc = cg + i;
                float h = b1s[k0g + cc];
                #pragma unroll
                for (int j = 0; j < 8; j++) h += qm[r * 9 + j] * w1s[j * 66 + cc];
                hs[r * HSP + cc] = __float2half(fmaxf(h, 0.f));
            }
        }
        __syncthreads();
        #pragma unroll
        for (int ks = 0; ks < 4; ks++) {
            unsigned a[2][4];
            #pragma unroll
            for (int mt = 0; mt < 2; mt++) {
                int mrow = wm * 32 + mt * 16;
                unsigned addr = hs_s + 2u * (unsigned)((mrow + l7 + 8 * (l3 & 1)) * HSP +
                                                       ks * 16 + 8 * (l3 >> 1));
                ldsm4(a[mt][0], a[mt][1], a[mt][2], a[mt][3], addr);
            }
            #pragma unroll
            for (int ng = 0; ng < 4; ng++) {
                int n0 = wn * 64 + ng * 16;
                unsigned baddr = ws_s + 2u * (unsigned)((ks * 16 + l7 + 8 * (l3 & 1)) * WSP +
                                                        n0 + 8 * (l3 >> 1));
                unsigned b0, b1r, b2r, b3;
                ldsm4t(b0, b1r, b2r, b3, baddr);
                MMA_F16(c[0][2*ng],   a[0][0], a[0][1], a[0][2], a[0][3], b0, b1r);
                MMA_F16(c[0][2*ng+1], a[0][0], a[0][1], a[0][2], a[0][3], b2r, b3);
                MMA_F16(c[1][2*ng],   a[1][0], a[1][1], a[1][2], a[1][3], b0, b1r);
                MMA_F16(c[1][2*ng+1], a[1][0], a[1][1], a[1][2], a[1][3], b2r, b3);
            }
        }
    }
    #pragma unroll
    for (int mt = 0; mt < 2; mt++) {
        int gr = rowBase + wm * 32 + mt * 16;
        #pragma unroll
        for (int nt = 0; nt < 8; nt++) {
            int col = wn * 64 + nt * 8 + 2 * tq;
            float bb0 = b2s[col], bb1 = b2s[col + 1];
            *(float2*)(d_a + (size_t)(gr + qt) * EE + col) =
                make_float2(c[mt][nt][0] + bb0, c[mt][nt][1] + bb1);
            *(float2*)(d_a + (size_t)(gr + qt + 8) * EE + col) =
                make_float2(c[mt][nt][2] + bb0, c[mt][nt][3] + bb1);
        }
    }
}

// ---------------- 5a. head partial sums: 64 rows per CTA ----------------
__global__ void psum_kernel() {
    int b = blockIdx.y, chunk = blockIdx.x;   // (32, 8)
    int e = threadIdx.x;
    const float* base = d_x + ((size_t)b * SS + chunk * 64) * EE + e;
    float s = 0.f;
    #pragma unroll 8
    for (int i = 0; i < 64; i++) s += base[(size_t)i * EE];
    d_part[((size_t)b * 32 + chunk) * EE + e] = s;
}

// ---------------- 5b. final mean + classifier head ----------------
__global__ void head_kernel(const float* __restrict__ Wc, const float* __restrict__ bc,
                            float* __restrict__ out) {
    __shared__ float mean[EE];
    int b = blockIdx.x;
    int e = threadIdx.x;
    const float* p = d_part + (size_t)b * 32 * EE + e;
    float s = 0.f;
    #pragma unroll
    for (int i = 0; i < 32; i++) s += p[i * EE];
    mean[e] = s * (1.f / SS);
    __syncthreads();
    if (e < NC) {
        float acc = bc[e];
        for (int ee = 0; ee < EE; ee++)
            acc += mean[ee] * Wc[ee * NC + e];
        out[b * NC + e] = acc;
    }
}

// ---------------- launch ----------------
extern "C" void kernel_launch(void* const* d_in, const int* in_sizes, int n_in,
                              void* d_out, int out_size) {
    const int*   tok   = (const int*)d_in[0];
    const float* emb   = (const float*)d_in[1];
    const float* phi   = (const float*)d_in[2];
    const float* theta = (const float*)d_in[3];
    const float* W1    = (const float*)d_in[4];
    const float* b1    = (const float*)d_in[5];
    const float* W2    = (const float*)d_in[6];
    const float* b2    = (const float*)d_in[7];
    const float* g1    = (const float*)d_in[8];
    const float* be1   = (const float*)d_in[9];
    const float* g2    = (const float*)d_in[10];
    const float* be2   = (const float*)d_in[11];
    const float* Wc    = (const float*)d_in[12];
    const float* bc    = (const float*)d_in[13];
    float* out = (float*)d_out;

    cudaFuncSetAttribute(attn_kernel, cudaFuncAttributeMaxDynamicSharedMemorySize, ATT_SMEM);
    cudaFuncSetAttribute(ffn_kernel, cudaFuncAttributeMaxDynamicSharedMemorySize, FFN_SMEM);

    w2cvt_kernel<<<LL * FF * EE / 4 / 256, 256>>>(W2);
    embed_q_kernel<<<ROWS * 32 / 256, 256>>>(tok, emb, phi);
    for (int l = 0; l < LL; l++) {
        attn_kernel<<<dim3(SS / 64, BB), 256, ATT_SMEM>>>(g1 + l * EE, be1 + l * EE);
        ffn_kernel<<<ROWS / 64, 256, FFN_SMEM>>>(theta + l * NQ, W1 + (size_t)l * NQ * FF,
                                                 b1 + l * FF, l, b2 + l * EE);
        addln_kernel<<<ROWS / 8, 256>>>(g2 + l * EE, be2 + l * EE,
                                        (l < LL - 1) ? (phi + (l + 1) * NQ) : nullptr);
    }
    psum_kernel<<<dim3(32, BB), 256>>>();
    head_kernel<<<BB, 256>>>(Wc, bc, out);
}